// round 11
// baseline (speedup 1.0000x reference)
#include <cuda_runtime.h>
#include <math.h>
#include <stdint.h>

// Problem constants
#define BB   8
#define CC   128
#define HH   64
#define WW   64
#define HW   4096           // 64*64
#define PAD  8              // zero border (absorbs deform offsets, no clamps)
#define WP   80             // padded width/height
#define HWP  (80 * 80)      // padded spatial (6400)
#define OCC  18             // offset conv output channels
#define KK9  9
#define CIKK 1152           // 128*9
#define DT   32             // pixels per deform block
#define NJ   (KK9 * DT)     // 288 sampling points per block
#define CICH 16             // ci channels per chunk (144 cik rows, 18 ksteps)
#define PSTR 148            // per-pixel row stride in sample tile (floats)
#define NKSTEP 144          // total k-steps (1152 / 8)

// ---------------- device scratch (no allocations allowed) ----------------
__device__ float g_off1[BB * OCC * HW];
__device__ float g_off2[BB * OCC * HW];
__device__ float g_out1[BB * CC * HW];
__device__ float g_xt  [BB * HWP * CC];         // padded NHWC staging
__device__ float g_wf1 [NKSTEP * 8 * 32 * 4];   // fragment-packed tf32 deform W
__device__ float g_wf2 [NKSTEP * 8 * 32 * 4];
__device__ float g_wo1 [NKSTEP * 2 * 32 * 4];   // fragment-packed offset W (pad 32)
__device__ float g_wo2 [NKSTEP * 2 * 32 * 4];

// round f32 -> tf32 (rna), result has low 13 mantissa bits zero
__device__ __forceinline__ float f2tf32(float f) {
    uint32_t u;
    asm("cvt.rna.tf32.f32 %0, %1;" : "=r"(u) : "f"(f));
    return __uint_as_float(u);
}

// m16n8k8 tf32 mma: D += A * B  (A row-major m16k8, B col-major k8n8)
__device__ __forceinline__ void mma_tf32(float* d,
                                         uint32_t a0, uint32_t a1,
                                         uint32_t a2, uint32_t a3,
                                         uint32_t b0, uint32_t b1) {
    asm volatile(
        "mma.sync.aligned.m16n8k8.row.col.f32.tf32.tf32.f32 "
        "{%0,%1,%2,%3}, {%4,%5,%6,%7}, {%8,%9}, {%0,%1,%2,%3};"
        : "+f"(d[0]), "+f"(d[1]), "+f"(d[2]), "+f"(d[3])
        : "r"(a0), "r"(a1), "r"(a2), "r"(a3), "r"(b0), "r"(b1));
}

// ---------------- zero the whole padded buffer (border must be 0) ----------
__global__ void zeropad_kernel()
{
    int idx = blockIdx.x * 512 + threadIdx.x;       // float4 index
    ((float4*)g_xt)[idx] = make_float4(0.f, 0.f, 0.f, 0.f);
}

// ---------------- deform weight prepack: [co][cik] -> mma A-fragment order --
__global__ void prepack_kernel(const float* __restrict__ w1,
                               const float* __restrict__ w2)
{
    int s    = blockIdx.x;          // 0..143
    int m    = threadIdx.x >> 5;    // 0..7
    int lane = threadIdx.x & 31;
    int gid  = lane >> 2, tig = lane & 3;
    int co0  = m * 16 + gid;
    int k0   = s * 8 + tig;
    int oidx = ((s * 8 + m) * 32 + lane) * 4;

    float4 v;
    v.x = f2tf32(w1[co0 * CIKK + k0]);
    v.y = f2tf32(w1[(co0 + 8) * CIKK + k0]);
    v.z = f2tf32(w1[co0 * CIKK + k0 + 4]);
    v.w = f2tf32(w1[(co0 + 8) * CIKK + k0 + 4]);
    *(float4*)&g_wf1[oidx] = v;

    v.x = f2tf32(w2[co0 * CIKK + k0]);
    v.y = f2tf32(w2[(co0 + 8) * CIKK + k0]);
    v.z = f2tf32(w2[co0 * CIKK + k0 + 4]);
    v.w = f2tf32(w2[(co0 + 8) * CIKK + k0 + 4]);
    *(float4*)&g_wf2[oidx] = v;
}

// ---------------- offset weight prepack: [18][cik] -> fragments, pad M to 32
__global__ void prepack_off_kernel(const float* __restrict__ w1,
                                   const float* __restrict__ w2)
{
    int s    = blockIdx.x;          // 0..143
    int m    = threadIdx.x >> 5;    // 0..1
    int lane = threadIdx.x & 31;
    int gid  = lane >> 2, tig = lane & 3;
    int coa  = m * 16 + gid;
    int cob  = coa + 8;
    int k0   = s * 8 + tig;
    int oidx = ((s * 2 + m) * 32 + lane) * 4;

    float4 v;
    v.x = (coa < OCC) ? f2tf32(w1[coa * CIKK + k0])     : 0.f;
    v.y = (cob < OCC) ? f2tf32(w1[cob * CIKK + k0])     : 0.f;
    v.z = (coa < OCC) ? f2tf32(w1[coa * CIKK + k0 + 4]) : 0.f;
    v.w = (cob < OCC) ? f2tf32(w1[cob * CIKK + k0 + 4]) : 0.f;
    *(float4*)&g_wo1[oidx] = v;

    v.x = (coa < OCC) ? f2tf32(w2[coa * CIKK + k0])     : 0.f;
    v.y = (cob < OCC) ? f2tf32(w2[cob * CIKK + k0])     : 0.f;
    v.z = (coa < OCC) ? f2tf32(w2[coa * CIKK + k0 + 4]) : 0.f;
    v.w = (cob < OCC) ? f2tf32(w2[cob * CIKK + k0 + 4]) : 0.f;
    *(float4*)&g_wo2[oidx] = v;
}

// ---------------- NCHW -> padded NHWC transpose ----------------
__global__ void transpose_kernel(const float* __restrict__ in, float* __restrict__ out)
{
    __shared__ float tile[32][33];
    int b  = blockIdx.z;
    int c0 = blockIdx.y * 32;
    int p0 = blockIdx.x * 32;
    int tx = threadIdx.x, ty = threadIdx.y;   // (32, 8)
    const float* ib = in + b * CC * HW;
    float* ob = out + b * HWP * CC;
    #pragma unroll
    for (int k = 0; k < 4; k++) {
        int c = c0 + ty + k * 8;
        tile[ty + k * 8][tx] = ib[c * HW + p0 + tx];
    }
    __syncthreads();
    #pragma unroll
    for (int k = 0; k < 4; k++) {
        int p = p0 + ty + k * 8;
        int pp = ((p >> 6) + PAD) * WP + (p & 63) + PAD;   // padded interior
        ob[pp * CC + c0 + tx] = tile[tx][ty + k * 8];
    }
}

// ---------------- offset conv via tf32 tensor cores (padded NHWC) -----------
__global__ __launch_bounds__(128, 6) void offconv_tc_kernel(
    const float* __restrict__ xt,      // padded NHWC input
    const float* __restrict__ wof,     // fragment-packed tf32 offset weights
    const float* __restrict__ bias,
    float* __restrict__ off)           // [b][18][hw]
{
    __shared__ float s_hi[DT * PSTR];  // [pix][cik_local]
    __shared__ float s_lo[DT * PSTR];

    int bx   = blockIdx.x;
    int b    = bx >> 7;
    int pix0 = (bx & 127) << 5;
    int tid  = threadIdx.x;

    int lane = tid & 31;
    int w    = tid >> 5;               // warp 0..3 = n-tile
    int gid  = lane >> 2;
    int tig  = lane & 3;

    float d[2][4];                     // [mtile][reg]
    #pragma unroll
    for (int mi = 0; mi < 2; mi++)
        #pragma unroll
        for (int r = 0; r < 4; r++)
            d[mi][r] = 0.f;

    int cil = tid & 15;
    int jg  = tid >> 4;                // 0..7: pixel t = jg + 8*i
    const float* xb0 = xt + b * HWP * CC + cil;
    const float4* wo4 = (const float4*)wof;

    // per-pixel padded bases (4 pixels per thread), computed once
    int pbase_r[4];
    #pragma unroll
    for (int i = 0; i < 4; i++) {
        int pix = pix0 + jg + i * 8;
        pbase_r[i] = (((pix >> 6) + PAD) * WP + (pix & 63) + PAD) * CC;
    }

    for (int chunk = 0; chunk < CC / CICH; chunk++) {
        __syncthreads();

        // gather: 9 taps per pixel at compile-time offsets off one base
        {
            const float* xb = xb0 + chunk * CICH;
            #pragma unroll
            for (int i = 0; i < 4; i++) {
                int t = jg + i * 8;
                const float* xp = xb + pbase_r[i];
                int idx0 = t * PSTR + cil * KK9;
                #pragma unroll
                for (int kk = 0; kk < KK9; kk++) {
                    const int dk = ((kk / 3 - 1) * WP + (kk % 3 - 1)) * CC;
                    float s = xp[dk];
                    float shi = f2tf32(s);
                    s_hi[idx0 + kk] = shi;
                    s_lo[idx0 + kk] = s - shi;
                }
            }
        }
        __syncthreads();

        #pragma unroll 2
        for (int sl = 0; sl < 18; sl++) {
            int s = chunk * 18 + sl;
            int aidx = (s * 2) * 32 + lane;
            float4 a0 = wo4[aidx];
            float4 a1 = wo4[aidx + 32];
            uint32_t a0x = __float_as_uint(a0.x), a0y = __float_as_uint(a0.y);
            uint32_t a0z = __float_as_uint(a0.z), a0w = __float_as_uint(a0.w);
            uint32_t a1x = __float_as_uint(a1.x), a1y = __float_as_uint(a1.y);
            uint32_t a1z = __float_as_uint(a1.z), a1w = __float_as_uint(a1.w);

            int krow = sl * 8 + tig;
            int p = (w * 8 + gid) * PSTR + krow;
            uint32_t bh0 = __float_as_uint(s_hi[p]);
            uint32_t bh1 = __float_as_uint(s_hi[p + 4]);
            uint32_t bl0 = __float_as_uint(s_lo[p]);
            uint32_t bl1 = __float_as_uint(s_lo[p + 4]);
            mma_tf32(d[0], a0x, a0y, a0z, a0w, bh0, bh1);
            mma_tf32(d[0], a0x, a0y, a0z, a0w, bl0, bl1);
            mma_tf32(d[1], a1x, a1y, a1z, a1w, bh0, bh1);
            mma_tf32(d[1], a1x, a1y, a1z, a1w, bl0, bl1);
        }
    }

    // epilogue: + bias, store rows co < 18. pixel = pix0 + w*8 + tig*2 + {0,1}
    int pbase = pix0 + w * 8 + tig * 2;
    #pragma unroll
    for (int mi = 0; mi < 2; mi++) {
        int coa = mi * 16 + gid;
        int cob = coa + 8;
        if (coa < OCC) {
            float bv = bias[coa];
            float2 r; r.x = d[mi][0] + bv; r.y = d[mi][1] + bv;
            *(float2*)(off + ((b * OCC + coa) << 12) + pbase) = r;
        }
        if (cob < OCC) {
            float bv = bias[cob];
            float2 r; r.x = d[mi][2] + bv; r.y = d[mi][3] + bv;
            *(float2*)(off + ((b * OCC + cob) << 12) + pbase) = r;
        }
    }
}

// ---------------- deform conv via tf32 tensor cores + BN (+resid) + ReLU ----
// Zero border (PAD=8) absorbs out-of-range bilinear taps: no clamps, no
// validity masks, single base offset per sampling point.
__global__ __launch_bounds__(128, 5) void deform_kernel(
    const float* __restrict__ xt,      // padded NHWC input
    const float* __restrict__ off,     // [b][18][hw]
    const float* __restrict__ wf,      // fragment-packed tf32 weights
    const float* __restrict__ gamma, const float* __restrict__ beta,
    const float* __restrict__ mean,  const float* __restrict__ var,
    const float* __restrict__ resid,   // nullptr for stage 1
    float* __restrict__ out)           // NCHW
{
    __shared__ float  s_hi[DT * PSTR];   // 18944 B
    __shared__ float  s_lo[DT * PSTR];   // 18944 B
    __shared__ int    s_o[NJ];           // tap base offsets (1152 B)
    __shared__ float4 s_w[NJ];           // bilinear weights (4608 B)

    int bx   = blockIdx.x;
    int b    = bx >> 7;
    int pix0 = (bx & 127) << 5;
    int tid  = threadIdx.x;

    // ---- sampling coordinates: j = kk*32 + t ----
    for (int j = tid; j < NJ; j += 128) {
        int kk = j >> 5;
        int t  = j & 31;
        int pix = pix0 + t;
        int h = pix >> 6;
        int w = pix & 63;
        int ky = kk / 3, kx = kk % 3;
        const float* ob = off + b * OCC * HW;
        float dy = ob[(2 * kk)     * HW + pix];
        float dx = ob[(2 * kk + 1) * HW + pix];
        float ys = (float)(h - 2 + 2 * ky) + dy;
        float xs = (float)(w - 2 + 2 * kx) + dx;
        float y0f = floorf(ys), x0f = floorf(xs);
        int y0 = (int)y0f, x0 = (int)x0f;
        float fy = ys - y0f, fx = xs - x0f;
        s_o[j] = ((y0 + PAD) * WP + x0 + PAD) * CC;
        float4 wv;
        wv.x = (1.f - fy) * (1.f - fx);
        wv.y = (1.f - fy) * fx;
        wv.z = fy * (1.f - fx);
        wv.w = fy * fx;
        s_w[j] = wv;
    }

    int lane = tid & 31;
    int w    = tid >> 5;
    int gid  = lane >> 2;
    int tig  = lane & 3;

    float d[2][4][4];
    #pragma unroll
    for (int mi = 0; mi < 2; mi++)
        #pragma unroll
        for (int nt = 0; nt < 4; nt++)
            #pragma unroll
            for (int r = 0; r < 4; r++)
                d[mi][nt][r] = 0.f;

    int cil = tid & 15;
    int jg  = tid >> 4;
    const float* xb0 = xt + b * HWP * CC + cil;
    const float4* wf4 = (const float4*)wf;

    for (int chunk = 0; chunk < CC / CICH; chunk++) {
        __syncthreads();

        {
            const float* xb = xb0 + chunk * CICH;
            for (int j = jg; j < NJ; j += 8) {
                int    o  = s_o[j];
                float4 wv = s_w[j];
                float v00 = xb[o];
                float v01 = xb[o + CC];
                float v10 = xb[o + WP * CC];
                float v11 = xb[o + WP * CC + CC];
                float s = wv.x * v00 + wv.y * v01 + wv.z * v10 + wv.w * v11;
                float shi = f2tf32(s);
                int kk = j >> 5;
                int t  = j & 31;
                int idx = t * PSTR + cil * KK9 + kk;
                s_hi[idx] = shi;
                s_lo[idx] = s - shi;
            }
        }
        __syncthreads();

        #pragma unroll 2
        for (int sl = 0; sl < 18; sl++) {
            int s = chunk * 18 + sl;
            int aidx = (s * 8 + w * 2) * 32 + lane;
            float4 a0 = wf4[aidx];
            float4 a1 = wf4[aidx + 32];
            uint32_t a0x = __float_as_uint(a0.x), a0y = __float_as_uint(a0.y);
            uint32_t a0z = __float_as_uint(a0.z), a0w = __float_as_uint(a0.w);
            uint32_t a1x = __float_as_uint(a1.x), a1y = __float_as_uint(a1.y);
            uint32_t a1z = __float_as_uint(a1.z), a1w = __float_as_uint(a1.w);

            int krow = sl * 8 + tig;
            #pragma unroll
            for (int nt = 0; nt < 4; nt++) {
                int p = (nt * 8 + gid) * PSTR + krow;
                uint32_t bh0 = __float_as_uint(s_hi[p]);
                uint32_t bh1 = __float_as_uint(s_hi[p + 4]);
                uint32_t bl0 = __float_as_uint(s_lo[p]);
                uint32_t bl1 = __float_as_uint(s_lo[p + 4]);
                mma_tf32(d[0][nt], a0x, a0y, a0z, a0w, bh0, bh1);
                mma_tf32(d[0][nt], a0x, a0y, a0z, a0w, bl0, bl1);
                mma_tf32(d[1][nt], a1x, a1y, a1z, a1w, bh0, bh1);
                mma_tf32(d[1][nt], a1x, a1y, a1z, a1w, bl0, bl1);
            }
        }
    }

    // ---- BN (+residual) + ReLU epilogue, NCHW float2 stores ----
    #pragma unroll
    for (int mi = 0; mi < 2; mi++) {
        int coa = w * 32 + mi * 16 + gid;
        int cob = coa + 8;
        float inva = gamma[coa] * rsqrtf(var[coa] + 1e-5f);
        float adda = beta[coa] - mean[coa] * inva;
        float invb = gamma[cob] * rsqrtf(var[cob] + 1e-5f);
        float addb = beta[cob] - mean[cob] * invb;
        int basea = ((b * CC + coa) << 12) + pix0 + tig * 2;
        int baseb = ((b * CC + cob) << 12) + pix0 + tig * 2;
        #pragma unroll
        for (int nt = 0; nt < 4; nt++) {
            float2 ra, rb;
            ra.x = d[mi][nt][0] * inva + adda;
            ra.y = d[mi][nt][1] * inva + adda;
            rb.x = d[mi][nt][2] * invb + addb;
            rb.y = d[mi][nt][3] * invb + addb;
            if (resid) {
                float2 qa = *(const float2*)(resid + basea + nt * 8);
                float2 qb = *(const float2*)(resid + baseb + nt * 8);
                ra.x += qa.x; ra.y += qa.y;
                rb.x += qb.x; rb.y += qb.y;
            }
            ra.x = fmaxf(ra.x, 0.f); ra.y = fmaxf(ra.y, 0.f);
            rb.x = fmaxf(rb.x, 0.f); rb.y = fmaxf(rb.y, 0.f);
            *(float2*)(out + basea + nt * 8) = ra;
            *(float2*)(out + baseb + nt * 8) = rb;
        }
    }
}

// ---------------- launch ----------------
extern "C" void kernel_launch(void* const* d_in, const int* in_sizes, int n_in,
                              void* d_out, int out_size)
{
    const float* x      = (const float*)d_in[0];
    const float* w_off1 = (const float*)d_in[1];
    const float* b_off1 = (const float*)d_in[2];
    const float* w_dc1  = (const float*)d_in[3];
    const float* g1     = (const float*)d_in[4];
    const float* beta1  = (const float*)d_in[5];
    const float* m1     = (const float*)d_in[6];
    const float* v1     = (const float*)d_in[7];
    const float* w_off2 = (const float*)d_in[8];
    const float* b_off2 = (const float*)d_in[9];
    const float* w_dc2  = (const float*)d_in[10];
    const float* g2     = (const float*)d_in[11];
    const float* beta2  = (const float*)d_in[12];
    const float* m2     = (const float*)d_in[13];
    const float* v2     = (const float*)d_in[14];
    float* out = (float*)d_out;

    float *off1, *off2, *out1, *xt, *wf1, *wf2, *wo1, *wo2;
    cudaGetSymbolAddress((void**)&off1, g_off1);
    cudaGetSymbolAddress((void**)&off2, g_off2);
    cudaGetSymbolAddress((void**)&out1, g_out1);
    cudaGetSymbolAddress((void**)&xt,   g_xt);
    cudaGetSymbolAddress((void**)&wf1,  g_wf1);
    cudaGetSymbolAddress((void**)&wf2,  g_wf2);
    cudaGetSymbolAddress((void**)&wo1,  g_wo1);
    cudaGetSymbolAddress((void**)&wo2,  g_wo2);

    dim3 trGrid(HW / 32, CC / 32, BB), trBlk(32, 8);

    // zero whole padded buffer (border stays 0; interior rewritten below)
    zeropad_kernel<<<(BB * HWP * CC / 4) / 512, 512>>>();
    prepack_kernel<<<NKSTEP, 256>>>(w_dc1, w_dc2);
    prepack_off_kernel<<<NKSTEP, 64>>>(w_off1, w_off2);

    // stage 1: transpose first, offconv reads padded NHWC
    transpose_kernel<<<trGrid, trBlk>>>(x, xt);
    offconv_tc_kernel<<<BB * HW / DT, 128>>>(xt, wo1, b_off1, off1);
    deform_kernel<<<BB * HW / DT, 128>>>(xt, off1, wf1, g1, beta1, m1, v1,
                                         nullptr, out1);
    // stage 2
    transpose_kernel<<<trGrid, trBlk>>>(out1, xt);
    offconv_tc_kernel<<<BB * HW / DT, 128>>>(xt, wo2, b_off2, off2);
    deform_kernel<<<BB * HW / DT, 128>>>(xt, off2, wf2, g2, beta2, m2, v2,
                                         x, out);
}

// round 12
// speedup vs baseline: 1.1599x; 1.1599x over previous
#include <cuda_runtime.h>
#include <math.h>
#include <stdint.h>

// Problem constants
#define BB   8
#define CC   128
#define HH   64
#define WW   64
#define HW   4096           // 64*64
#define PAD  8              // zero border (absorbs deform offsets, no clamps)
#define WP   80             // padded width/height
#define HWP  (80 * 80)      // padded spatial (6400)
#define OCC  18             // offset conv output channels
#define KK9  9
#define CIKK 1152           // 128*9
#define DT   32             // pixels per deform block
#define NJ   (KK9 * DT)     // 288 sampling points per block
#define CICH 16             // ci channels per chunk (144 cik rows, 18 ksteps)
#define PSTR 148            // per-pixel row stride in sample tile (floats)
#define NKSTEP 144          // total k-steps (1152 / 8)

// ---------------- device scratch (no allocations allowed) ----------------
__device__ float g_off1[BB * OCC * HW];
__device__ float g_off2[BB * OCC * HW];
__device__ float g_out1[BB * CC * HW];
__device__ float g_xt  [BB * HWP * CC];         // padded NHWC staging
__device__ float g_wf1 [NKSTEP * 8 * 32 * 4];   // fragment-packed tf32 deform W
__device__ float g_wf2 [NKSTEP * 8 * 32 * 4];
__device__ float g_wo1 [NKSTEP * 2 * 32 * 4];   // fragment-packed offset W (pad 32)
__device__ float g_wo2 [NKSTEP * 2 * 32 * 4];

// round f32 -> tf32 (rna), result has low 13 mantissa bits zero
__device__ __forceinline__ float f2tf32(float f) {
    uint32_t u;
    asm("cvt.rna.tf32.f32 %0, %1;" : "=r"(u) : "f"(f));
    return __uint_as_float(u);
}

// m16n8k8 tf32 mma: D += A * B  (A row-major m16k8, B col-major k8n8)
__device__ __forceinline__ void mma_tf32(float* d,
                                         uint32_t a0, uint32_t a1,
                                         uint32_t a2, uint32_t a3,
                                         uint32_t b0, uint32_t b1) {
    asm volatile(
        "mma.sync.aligned.m16n8k8.row.col.f32.tf32.tf32.f32 "
        "{%0,%1,%2,%3}, {%4,%5,%6,%7}, {%8,%9}, {%0,%1,%2,%3};"
        : "+f"(d[0]), "+f"(d[1]), "+f"(d[2]), "+f"(d[3])
        : "r"(a0), "r"(a1), "r"(a2), "r"(a3), "r"(b0), "r"(b1));
}

// ---------------- zero the whole padded buffer (border must be 0) ----------
__global__ void zeropad_kernel()
{
    int idx = blockIdx.x * 512 + threadIdx.x;       // float4 index
    ((float4*)g_xt)[idx] = make_float4(0.f, 0.f, 0.f, 0.f);
}

// ---------------- deform weight prepack: [co][cik] -> mma A-fragment order --
__global__ void prepack_kernel(const float* __restrict__ w1,
                               const float* __restrict__ w2)
{
    int s    = blockIdx.x;          // 0..143
    int m    = threadIdx.x >> 5;    // 0..7
    int lane = threadIdx.x & 31;
    int gid  = lane >> 2, tig = lane & 3;
    int co0  = m * 16 + gid;
    int k0   = s * 8 + tig;
    int oidx = ((s * 8 + m) * 32 + lane) * 4;

    float4 v;
    v.x = f2tf32(w1[co0 * CIKK + k0]);
    v.y = f2tf32(w1[(co0 + 8) * CIKK + k0]);
    v.z = f2tf32(w1[co0 * CIKK + k0 + 4]);
    v.w = f2tf32(w1[(co0 + 8) * CIKK + k0 + 4]);
    *(float4*)&g_wf1[oidx] = v;

    v.x = f2tf32(w2[co0 * CIKK + k0]);
    v.y = f2tf32(w2[(co0 + 8) * CIKK + k0]);
    v.z = f2tf32(w2[co0 * CIKK + k0 + 4]);
    v.w = f2tf32(w2[(co0 + 8) * CIKK + k0 + 4]);
    *(float4*)&g_wf2[oidx] = v;
}

// ---------------- offset weight prepack: [18][cik] -> fragments, pad M to 32
__global__ void prepack_off_kernel(const float* __restrict__ w1,
                                   const float* __restrict__ w2)
{
    int s    = blockIdx.x;          // 0..143
    int m    = threadIdx.x >> 5;    // 0..1
    int lane = threadIdx.x & 31;
    int gid  = lane >> 2, tig = lane & 3;
    int coa  = m * 16 + gid;
    int cob  = coa + 8;
    int k0   = s * 8 + tig;
    int oidx = ((s * 2 + m) * 32 + lane) * 4;

    float4 v;
    v.x = (coa < OCC) ? f2tf32(w1[coa * CIKK + k0])     : 0.f;
    v.y = (cob < OCC) ? f2tf32(w1[cob * CIKK + k0])     : 0.f;
    v.z = (coa < OCC) ? f2tf32(w1[coa * CIKK + k0 + 4]) : 0.f;
    v.w = (cob < OCC) ? f2tf32(w1[cob * CIKK + k0 + 4]) : 0.f;
    *(float4*)&g_wo1[oidx] = v;

    v.x = (coa < OCC) ? f2tf32(w2[coa * CIKK + k0])     : 0.f;
    v.y = (cob < OCC) ? f2tf32(w2[cob * CIKK + k0])     : 0.f;
    v.z = (coa < OCC) ? f2tf32(w2[coa * CIKK + k0 + 4]) : 0.f;
    v.w = (cob < OCC) ? f2tf32(w2[cob * CIKK + k0 + 4]) : 0.f;
    *(float4*)&g_wo2[oidx] = v;
}

// ---------------- NCHW -> padded NHWC transpose ----------------
__global__ void transpose_kernel(const float* __restrict__ in, float* __restrict__ out)
{
    __shared__ float tile[32][33];
    int b  = blockIdx.z;
    int c0 = blockIdx.y * 32;
    int p0 = blockIdx.x * 32;
    int tx = threadIdx.x, ty = threadIdx.y;   // (32, 8)
    const float* ib = in + b * CC * HW;
    float* ob = out + b * HWP * CC;
    #pragma unroll
    for (int k = 0; k < 4; k++) {
        int c = c0 + ty + k * 8;
        tile[ty + k * 8][tx] = ib[c * HW + p0 + tx];
    }
    __syncthreads();
    #pragma unroll
    for (int k = 0; k < 4; k++) {
        int p = p0 + ty + k * 8;
        int pp = ((p >> 6) + PAD) * WP + (p & 63) + PAD;   // padded interior
        ob[pp * CC + c0 + tx] = tile[tx][ty + k * 8];
    }
}

// ---------------- offset conv via tf32 tensor cores (padded NHWC) -----------
__global__ __launch_bounds__(128, 6) void offconv_tc_kernel(
    const float* __restrict__ xt,      // padded NHWC input
    const float* __restrict__ wof,     // fragment-packed tf32 offset weights
    const float* __restrict__ bias,
    float* __restrict__ off)           // [b][18][hw]
{
    __shared__ float s_hi[DT * PSTR];  // [pix][cik_local]
    __shared__ float s_lo[DT * PSTR];

    int bx   = blockIdx.x;
    int b    = bx >> 7;
    int pix0 = (bx & 127) << 5;
    int tid  = threadIdx.x;

    int lane = tid & 31;
    int w    = tid >> 5;               // warp 0..3 = n-tile
    int gid  = lane >> 2;
    int tig  = lane & 3;

    float d[2][4];                     // [mtile][reg]
    #pragma unroll
    for (int mi = 0; mi < 2; mi++)
        #pragma unroll
        for (int r = 0; r < 4; r++)
            d[mi][r] = 0.f;

    int cil = tid & 15;
    int jg  = tid >> 4;                // 0..7: pixel t = jg + 8*i
    const float* xb0 = xt + b * HWP * CC + cil;
    const float4* wo4 = (const float4*)wof;

    // per-pixel padded bases (4 pixels per thread), computed once
    int pbase_r[4];
    #pragma unroll
    for (int i = 0; i < 4; i++) {
        int pix = pix0 + jg + i * 8;
        pbase_r[i] = (((pix >> 6) + PAD) * WP + (pix & 63) + PAD) * CC;
    }

    for (int chunk = 0; chunk < CC / CICH; chunk++) {
        __syncthreads();

        // gather: 9 taps per pixel at compile-time offsets off one base
        {
            const float* xb = xb0 + chunk * CICH;
            #pragma unroll
            for (int i = 0; i < 4; i++) {
                int t = jg + i * 8;
                const float* xp = xb + pbase_r[i];
                int idx0 = t * PSTR + cil * KK9;
                #pragma unroll
                for (int kk = 0; kk < KK9; kk++) {
                    const int dk = ((kk / 3 - 1) * WP + (kk % 3 - 1)) * CC;
                    float s = xp[dk];
                    float shi = f2tf32(s);
                    s_hi[idx0 + kk] = shi;
                    s_lo[idx0 + kk] = s - shi;
                }
            }
        }
        __syncthreads();

        #pragma unroll 2
        for (int sl = 0; sl < 18; sl++) {
            int s = chunk * 18 + sl;
            int aidx = (s * 2) * 32 + lane;
            float4 a0 = wo4[aidx];
            float4 a1 = wo4[aidx + 32];
            uint32_t a0x = __float_as_uint(a0.x), a0y = __float_as_uint(a0.y);
            uint32_t a0z = __float_as_uint(a0.z), a0w = __float_as_uint(a0.w);
            uint32_t a1x = __float_as_uint(a1.x), a1y = __float_as_uint(a1.y);
            uint32_t a1z = __float_as_uint(a1.z), a1w = __float_as_uint(a1.w);

            int krow = sl * 8 + tig;
            int p = (w * 8 + gid) * PSTR + krow;
            uint32_t bh0 = __float_as_uint(s_hi[p]);
            uint32_t bh1 = __float_as_uint(s_hi[p + 4]);
            uint32_t bl0 = __float_as_uint(s_lo[p]);
            uint32_t bl1 = __float_as_uint(s_lo[p + 4]);
            mma_tf32(d[0], a0x, a0y, a0z, a0w, bh0, bh1);
            mma_tf32(d[0], a0x, a0y, a0z, a0w, bl0, bl1);
            mma_tf32(d[1], a1x, a1y, a1z, a1w, bh0, bh1);
            mma_tf32(d[1], a1x, a1y, a1z, a1w, bl0, bl1);
        }
    }

    // epilogue: + bias, store rows co < 18. pixel = pix0 + w*8 + tig*2 + {0,1}
    int pbase = pix0 + w * 8 + tig * 2;
    #pragma unroll
    for (int mi = 0; mi < 2; mi++) {
        int coa = mi * 16 + gid;
        int cob = coa + 8;
        if (coa < OCC) {
            float bv = bias[coa];
            float2 r; r.x = d[mi][0] + bv; r.y = d[mi][1] + bv;
            *(float2*)(off + ((b * OCC + coa) << 12) + pbase) = r;
        }
        if (cob < OCC) {
            float bv = bias[cob];
            float2 r; r.x = d[mi][2] + bv; r.y = d[mi][3] + bv;
            *(float2*)(off + ((b * OCC + cob) << 12) + pbase) = r;
        }
    }
}

// ---------------- deform conv via tf32 tensor cores + BN (+resid) + ReLU ----
// Zero border (PAD=8): no clamps/masks. Single-pass tf32 samples (no lo
// compensation) -> half the MMAs and STS, 24.7 KB smem.
__global__ __launch_bounds__(128, 5) void deform_kernel(
    const float* __restrict__ xt,      // padded NHWC input
    const float* __restrict__ off,     // [b][18][hw]
    const float* __restrict__ wf,      // fragment-packed tf32 weights
    const float* __restrict__ gamma, const float* __restrict__ beta,
    const float* __restrict__ mean,  const float* __restrict__ var,
    const float* __restrict__ resid,   // nullptr for stage 1
    float* __restrict__ out)           // NCHW
{
    __shared__ float  s_hi[DT * PSTR];   // 18944 B
    __shared__ int    s_o[NJ];           // tap base offsets (1152 B)
    __shared__ float4 s_w[NJ];           // bilinear weights (4608 B)

    int bx   = blockIdx.x;
    int b    = bx >> 7;
    int pix0 = (bx & 127) << 5;
    int tid  = threadIdx.x;

    // ---- sampling coordinates: j = kk*32 + t ----
    for (int j = tid; j < NJ; j += 128) {
        int kk = j >> 5;
        int t  = j & 31;
        int pix = pix0 + t;
        int h = pix >> 6;
        int w = pix & 63;
        int ky = kk / 3, kx = kk % 3;
        const float* ob = off + b * OCC * HW;
        float dy = ob[(2 * kk)     * HW + pix];
        float dx = ob[(2 * kk + 1) * HW + pix];
        float ys = (float)(h - 2 + 2 * ky) + dy;
        float xs = (float)(w - 2 + 2 * kx) + dx;
        float y0f = floorf(ys), x0f = floorf(xs);
        int y0 = (int)y0f, x0 = (int)x0f;
        float fy = ys - y0f, fx = xs - x0f;
        s_o[j] = ((y0 + PAD) * WP + x0 + PAD) * CC;
        float4 wv;
        wv.x = (1.f - fy) * (1.f - fx);
        wv.y = (1.f - fy) * fx;
        wv.z = fy * (1.f - fx);
        wv.w = fy * fx;
        s_w[j] = wv;
    }

    int lane = tid & 31;
    int w    = tid >> 5;
    int gid  = lane >> 2;
    int tig  = lane & 3;

    float d[2][4][4];
    #pragma unroll
    for (int mi = 0; mi < 2; mi++)
        #pragma unroll
        for (int nt = 0; nt < 4; nt++)
            #pragma unroll
            for (int r = 0; r < 4; r++)
                d[mi][nt][r] = 0.f;

    int cil = tid & 15;
    int jg  = tid >> 4;
    const float* xb0 = xt + b * HWP * CC + cil;
    const float4* wf4 = (const float4*)wf;

    for (int chunk = 0; chunk < CC / CICH; chunk++) {
        __syncthreads();

        {
            const float* xb = xb0 + chunk * CICH;
            for (int j = jg; j < NJ; j += 8) {
                int    o  = s_o[j];
                float4 wv = s_w[j];
                float v00 = xb[o];
                float v01 = xb[o + CC];
                float v10 = xb[o + WP * CC];
                float v11 = xb[o + WP * CC + CC];
                float s = wv.x * v00 + wv.y * v01 + wv.z * v10 + wv.w * v11;
                int kk = j >> 5;
                int t  = j & 31;
                s_hi[t * PSTR + cil * KK9 + kk] = f2tf32(s);
            }
        }
        __syncthreads();

        #pragma unroll 2
        for (int sl = 0; sl < 18; sl++) {
            int s = chunk * 18 + sl;
            int aidx = (s * 8 + w * 2) * 32 + lane;
            float4 a0 = wf4[aidx];
            float4 a1 = wf4[aidx + 32];
            uint32_t a0x = __float_as_uint(a0.x), a0y = __float_as_uint(a0.y);
            uint32_t a0z = __float_as_uint(a0.z), a0w = __float_as_uint(a0.w);
            uint32_t a1x = __float_as_uint(a1.x), a1y = __float_as_uint(a1.y);
            uint32_t a1z = __float_as_uint(a1.z), a1w = __float_as_uint(a1.w);

            int krow = sl * 8 + tig;
            #pragma unroll
            for (int nt = 0; nt < 4; nt++) {
                int p = (nt * 8 + gid) * PSTR + krow;
                uint32_t bh0 = __float_as_uint(s_hi[p]);
                uint32_t bh1 = __float_as_uint(s_hi[p + 4]);
                mma_tf32(d[0][nt], a0x, a0y, a0z, a0w, bh0, bh1);
                mma_tf32(d[1][nt], a1x, a1y, a1z, a1w, bh0, bh1);
            }
        }
    }

    // ---- BN (+residual) + ReLU epilogue, NCHW float2 stores ----
    #pragma unroll
    for (int mi = 0; mi < 2; mi++) {
        int coa = w * 32 + mi * 16 + gid;
        int cob = coa + 8;
        float inva = gamma[coa] * rsqrtf(var[coa] + 1e-5f);
        float adda = beta[coa] - mean[coa] * inva;
        float invb = gamma[cob] * rsqrtf(var[cob] + 1e-5f);
        float addb = beta[cob] - mean[cob] * invb;
        int basea = ((b * CC + coa) << 12) + pix0 + tig * 2;
        int baseb = ((b * CC + cob) << 12) + pix0 + tig * 2;
        #pragma unroll
        for (int nt = 0; nt < 4; nt++) {
            float2 ra, rb;
            ra.x = d[mi][nt][0] * inva + adda;
            ra.y = d[mi][nt][1] * inva + adda;
            rb.x = d[mi][nt][2] * invb + addb;
            rb.y = d[mi][nt][3] * invb + addb;
            if (resid) {
                float2 qa = *(const float2*)(resid + basea + nt * 8);
                float2 qb = *(const float2*)(resid + baseb + nt * 8);
                ra.x += qa.x; ra.y += qa.y;
                rb.x += qb.x; rb.y += qb.y;
            }
            ra.x = fmaxf(ra.x, 0.f); ra.y = fmaxf(ra.y, 0.f);
            rb.x = fmaxf(rb.x, 0.f); rb.y = fmaxf(rb.y, 0.f);
            *(float2*)(out + basea + nt * 8) = ra;
            *(float2*)(out + baseb + nt * 8) = rb;
        }
    }
}

// ---------------- launch ----------------
extern "C" void kernel_launch(void* const* d_in, const int* in_sizes, int n_in,
                              void* d_out, int out_size)
{
    const float* x      = (const float*)d_in[0];
    const float* w_off1 = (const float*)d_in[1];
    const float* b_off1 = (const float*)d_in[2];
    const float* w_dc1  = (const float*)d_in[3];
    const float* g1     = (const float*)d_in[4];
    const float* beta1  = (const float*)d_in[5];
    const float* m1     = (const float*)d_in[6];
    const float* v1     = (const float*)d_in[7];
    const float* w_off2 = (const float*)d_in[8];
    const float* b_off2 = (const float*)d_in[9];
    const float* w_dc2  = (const float*)d_in[10];
    const float* g2     = (const float*)d_in[11];
    const float* beta2  = (const float*)d_in[12];
    const float* m2     = (const float*)d_in[13];
    const float* v2     = (const float*)d_in[14];
    float* out = (float*)d_out;

    float *off1, *off2, *out1, *xt, *wf1, *wf2, *wo1, *wo2;
    cudaGetSymbolAddress((void**)&off1, g_off1);
    cudaGetSymbolAddress((void**)&off2, g_off2);
    cudaGetSymbolAddress((void**)&out1, g_out1);
    cudaGetSymbolAddress((void**)&xt,   g_xt);
    cudaGetSymbolAddress((void**)&wf1,  g_wf1);
    cudaGetSymbolAddress((void**)&wf2,  g_wf2);
    cudaGetSymbolAddress((void**)&wo1,  g_wo1);
    cudaGetSymbolAddress((void**)&wo2,  g_wo2);

    dim3 trGrid(HW / 32, CC / 32, BB), trBlk(32, 8);

    // zero whole padded buffer (border stays 0; interior rewritten below)
    zeropad_kernel<<<(BB * HWP * CC / 4) / 512, 512>>>();
    prepack_kernel<<<NKSTEP, 256>>>(w_dc1, w_dc2);
    prepack_off_kernel<<<NKSTEP, 64>>>(w_off1, w_off2);

    // stage 1: transpose first, offconv reads padded NHWC
    transpose_kernel<<<trGrid, trBlk>>>(x, xt);
    offconv_tc_kernel<<<BB * HW / DT, 128>>>(xt, wo1, b_off1, off1);
    deform_kernel<<<BB * HW / DT, 128>>>(xt, off1, wf1, g1, beta1, m1, v1,
                                         nullptr, out1);
    // stage 2
    transpose_kernel<<<trGrid, trBlk>>>(out1, xt);
    offconv_tc_kernel<<<BB * HW / DT, 128>>>(xt, wo2, b_off2, off2);
    deform_kernel<<<BB * HW / DT, 128>>>(xt, off2, wf2, g2, beta2, m2, v2,
                                         x, out);
}

// round 13
// speedup vs baseline: 1.2804x; 1.1038x over previous
#include <cuda_runtime.h>
#include <math.h>
#include <stdint.h>

// Problem constants
#define BB   8
#define CC   128
#define HH   64
#define WW   64
#define HW   4096           // 64*64
#define PAD  8              // zero border (absorbs deform offsets, no clamps)
#define WP   80             // padded width/height
#define HWP  (80 * 80)      // padded spatial (6400)
#define OCC  18             // offset conv output channels
#define KK9  9
#define CIKK 1152           // 128*9
#define DT   32             // pixels per deform block
#define NJ   (KK9 * DT)     // 288 sampling points per block
#define CICH 16             // ci channels per chunk (144 cik rows, 18 ksteps)
#define PSTR 148            // per-pixel row stride in sample tile (floats)
#define NKSTEP 144          // total k-steps (1152 / 8)

// ---------------- device scratch (no allocations allowed) ----------------
__device__ float g_off1[BB * OCC * HW];
__device__ float g_off2[BB * OCC * HW];
__device__ float g_xt  [BB * HWP * CC];         // padded NHWC staging (stage 1 in)
__device__ float g_xt2 [BB * HWP * CC];         // padded NHWC stage-1 output
__device__ float g_wf1 [NKSTEP * 8 * 32 * 4];   // fragment-packed tf32 deform W
__device__ float g_wf2 [NKSTEP * 8 * 32 * 4];
__device__ float g_wo1 [NKSTEP * 2 * 32 * 4];   // fragment-packed offset W (pad 32)
__device__ float g_wo2 [NKSTEP * 2 * 32 * 4];

// round f32 -> tf32 (rna), result has low 13 mantissa bits zero
__device__ __forceinline__ float f2tf32(float f) {
    uint32_t u;
    asm("cvt.rna.tf32.f32 %0, %1;" : "=r"(u) : "f"(f));
    return __uint_as_float(u);
}

// m16n8k8 tf32 mma: D += A * B  (A row-major m16k8, B col-major k8n8)
__device__ __forceinline__ void mma_tf32(float* d,
                                         uint32_t a0, uint32_t a1,
                                         uint32_t a2, uint32_t a3,
                                         uint32_t b0, uint32_t b1) {
    asm volatile(
        "mma.sync.aligned.m16n8k8.row.col.f32.tf32.tf32.f32 "
        "{%0,%1,%2,%3}, {%4,%5,%6,%7}, {%8,%9}, {%0,%1,%2,%3};"
        : "+f"(d[0]), "+f"(d[1]), "+f"(d[2]), "+f"(d[3])
        : "r"(a0), "r"(a1), "r"(a2), "r"(a3), "r"(b0), "r"(b1));
}

// ---------------- zero a padded buffer (border must be 0) ----------
__global__ void zeropad_kernel(float* buf)
{
    int idx = blockIdx.x * 512 + threadIdx.x;       // float4 index
    ((float4*)buf)[idx] = make_float4(0.f, 0.f, 0.f, 0.f);
}

// ---------------- deform weight prepack: [co][cik] -> mma A-fragment order --
__global__ void prepack_kernel(const float* __restrict__ w1,
                               const float* __restrict__ w2)
{
    int s    = blockIdx.x;          // 0..143
    int m    = threadIdx.x >> 5;    // 0..7
    int lane = threadIdx.x & 31;
    int gid  = lane >> 2, tig = lane & 3;
    int co0  = m * 16 + gid;
    int k0   = s * 8 + tig;
    int oidx = ((s * 8 + m) * 32 + lane) * 4;

    float4 v;
    v.x = f2tf32(w1[co0 * CIKK + k0]);
    v.y = f2tf32(w1[(co0 + 8) * CIKK + k0]);
    v.z = f2tf32(w1[co0 * CIKK + k0 + 4]);
    v.w = f2tf32(w1[(co0 + 8) * CIKK + k0 + 4]);
    *(float4*)&g_wf1[oidx] = v;

    v.x = f2tf32(w2[co0 * CIKK + k0]);
    v.y = f2tf32(w2[(co0 + 8) * CIKK + k0]);
    v.z = f2tf32(w2[co0 * CIKK + k0 + 4]);
    v.w = f2tf32(w2[(co0 + 8) * CIKK + k0 + 4]);
    *(float4*)&g_wf2[oidx] = v;
}

// ---------------- offset weight prepack: [18][cik] -> fragments, pad M to 32
__global__ void prepack_off_kernel(const float* __restrict__ w1,
                                   const float* __restrict__ w2)
{
    int s    = blockIdx.x;          // 0..143
    int m    = threadIdx.x >> 5;    // 0..1
    int lane = threadIdx.x & 31;
    int gid  = lane >> 2, tig = lane & 3;
    int coa  = m * 16 + gid;
    int cob  = coa + 8;
    int k0   = s * 8 + tig;
    int oidx = ((s * 2 + m) * 32 + lane) * 4;

    float4 v;
    v.x = (coa < OCC) ? f2tf32(w1[coa * CIKK + k0])     : 0.f;
    v.y = (cob < OCC) ? f2tf32(w1[cob * CIKK + k0])     : 0.f;
    v.z = (coa < OCC) ? f2tf32(w1[coa * CIKK + k0 + 4]) : 0.f;
    v.w = (cob < OCC) ? f2tf32(w1[cob * CIKK + k0 + 4]) : 0.f;
    *(float4*)&g_wo1[oidx] = v;

    v.x = (coa < OCC) ? f2tf32(w2[coa * CIKK + k0])     : 0.f;
    v.y = (cob < OCC) ? f2tf32(w2[cob * CIKK + k0])     : 0.f;
    v.z = (coa < OCC) ? f2tf32(w2[coa * CIKK + k0 + 4]) : 0.f;
    v.w = (cob < OCC) ? f2tf32(w2[cob * CIKK + k0 + 4]) : 0.f;
    *(float4*)&g_wo2[oidx] = v;
}

// ---------------- NCHW -> padded NHWC transpose (stage 1 input only) --------
__global__ void transpose_kernel(const float* __restrict__ in, float* __restrict__ out)
{
    __shared__ float tile[32][33];
    int b  = blockIdx.z;
    int c0 = blockIdx.y * 32;
    int p0 = blockIdx.x * 32;
    int tx = threadIdx.x, ty = threadIdx.y;   // (32, 8)
    const float* ib = in + b * CC * HW;
    float* ob = out + b * HWP * CC;
    #pragma unroll
    for (int k = 0; k < 4; k++) {
        int c = c0 + ty + k * 8;
        tile[ty + k * 8][tx] = ib[c * HW + p0 + tx];
    }
    __syncthreads();
    #pragma unroll
    for (int k = 0; k < 4; k++) {
        int p = p0 + ty + k * 8;
        int pp = ((p >> 6) + PAD) * WP + (p & 63) + PAD;   // padded interior
        ob[pp * CC + c0 + tx] = tile[tx][ty + k * 8];
    }
}

// ---------------- offset conv via tf32 tensor cores (padded NHWC) -----------
// Single-pass tf32 samples (offsets tolerate ~1e-4 perturbation).
__global__ __launch_bounds__(128, 6) void offconv_tc_kernel(
    const float* __restrict__ xt,      // padded NHWC input
    const float* __restrict__ wof,     // fragment-packed tf32 offset weights
    const float* __restrict__ bias,
    float* __restrict__ off)           // [b][18][hw]
{
    __shared__ float s_hi[DT * PSTR];  // [pix][cik_local]

    int bx   = blockIdx.x;
    int b    = bx >> 7;
    int pix0 = (bx & 127) << 5;
    int tid  = threadIdx.x;

    int lane = tid & 31;
    int w    = tid >> 5;               // warp 0..3 = n-tile
    int gid  = lane >> 2;
    int tig  = lane & 3;

    float d[2][4];                     // [mtile][reg]
    #pragma unroll
    for (int mi = 0; mi < 2; mi++)
        #pragma unroll
        for (int r = 0; r < 4; r++)
            d[mi][r] = 0.f;

    int cil = tid & 15;
    int jg  = tid >> 4;                // 0..7: pixel t = jg + 8*i
    const float* xb0 = xt + b * HWP * CC + cil;
    const float4* wo4 = (const float4*)wof;

    // per-pixel padded bases (4 pixels per thread), computed once
    int pbase_r[4];
    #pragma unroll
    for (int i = 0; i < 4; i++) {
        int pix = pix0 + jg + i * 8;
        pbase_r[i] = (((pix >> 6) + PAD) * WP + (pix & 63) + PAD) * CC;
    }

    for (int chunk = 0; chunk < CC / CICH; chunk++) {
        __syncthreads();

        // gather: 9 taps per pixel at compile-time offsets off one base
        {
            const float* xb = xb0 + chunk * CICH;
            #pragma unroll
            for (int i = 0; i < 4; i++) {
                int t = jg + i * 8;
                const float* xp = xb + pbase_r[i];
                int idx0 = t * PSTR + cil * KK9;
                #pragma unroll
                for (int kk = 0; kk < KK9; kk++) {
                    const int dk = ((kk / 3 - 1) * WP + (kk % 3 - 1)) * CC;
                    s_hi[idx0 + kk] = f2tf32(xp[dk]);
                }
            }
        }
        __syncthreads();

        #pragma unroll 2
        for (int sl = 0; sl < 18; sl++) {
            int s = chunk * 18 + sl;
            int aidx = (s * 2) * 32 + lane;
            float4 a0 = wo4[aidx];
            float4 a1 = wo4[aidx + 32];
            uint32_t a0x = __float_as_uint(a0.x), a0y = __float_as_uint(a0.y);
            uint32_t a0z = __float_as_uint(a0.z), a0w = __float_as_uint(a0.w);
            uint32_t a1x = __float_as_uint(a1.x), a1y = __float_as_uint(a1.y);
            uint32_t a1z = __float_as_uint(a1.z), a1w = __float_as_uint(a1.w);

            int krow = sl * 8 + tig;
            int p = (w * 8 + gid) * PSTR + krow;
            uint32_t bh0 = __float_as_uint(s_hi[p]);
            uint32_t bh1 = __float_as_uint(s_hi[p + 4]);
            mma_tf32(d[0], a0x, a0y, a0z, a0w, bh0, bh1);
            mma_tf32(d[1], a1x, a1y, a1z, a1w, bh0, bh1);
        }
    }

    // epilogue: + bias, store rows co < 18. pixel = pix0 + w*8 + tig*2 + {0,1}
    int pbase = pix0 + w * 8 + tig * 2;
    #pragma unroll
    for (int mi = 0; mi < 2; mi++) {
        int coa = mi * 16 + gid;
        int cob = coa + 8;
        if (coa < OCC) {
            float bv = bias[coa];
            float2 r; r.x = d[mi][0] + bv; r.y = d[mi][1] + bv;
            *(float2*)(off + ((b * OCC + coa) << 12) + pbase) = r;
        }
        if (cob < OCC) {
            float bv = bias[cob];
            float2 r; r.x = d[mi][2] + bv; r.y = d[mi][3] + bv;
            *(float2*)(off + ((b * OCC + cob) << 12) + pbase) = r;
        }
    }
}

// ---------------- deform conv via tf32 tensor cores + BN (+resid) + ReLU ----
// out_nhwc != nullptr: write padded-NHWC (stage 1, feeds stage 2 directly).
// else: write NCHW `out` with optional NCHW residual (stage 2).
__global__ __launch_bounds__(128, 5) void deform_kernel(
    const float* __restrict__ xt,      // padded NHWC input
    const float* __restrict__ off,     // [b][18][hw]
    const float* __restrict__ wf,      // fragment-packed tf32 weights
    const float* __restrict__ gamma, const float* __restrict__ beta,
    const float* __restrict__ mean,  const float* __restrict__ var,
    const float* __restrict__ resid,   // NCHW residual or nullptr
    float* __restrict__ out,           // NCHW output (stage 2)
    float* __restrict__ out_nhwc)      // padded NHWC output (stage 1)
{
    __shared__ float  s_hi[DT * PSTR];   // 18944 B
    __shared__ int    s_o[NJ];           // tap base offsets (1152 B)
    __shared__ float4 s_w[NJ];           // bilinear weights (4608 B)

    int bx   = blockIdx.x;
    int b    = bx >> 7;
    int pix0 = (bx & 127) << 5;
    int tid  = threadIdx.x;

    // ---- sampling coordinates: j = kk*32 + t ----
    for (int j = tid; j < NJ; j += 128) {
        int kk = j >> 5;
        int t  = j & 31;
        int pix = pix0 + t;
        int h = pix >> 6;
        int w = pix & 63;
        int ky = kk / 3, kx = kk % 3;
        const float* ob = off + b * OCC * HW;
        float dy = ob[(2 * kk)     * HW + pix];
        float dx = ob[(2 * kk + 1) * HW + pix];
        float ys = (float)(h - 2 + 2 * ky) + dy;
        float xs = (float)(w - 2 + 2 * kx) + dx;
        float y0f = floorf(ys), x0f = floorf(xs);
        int y0 = (int)y0f, x0 = (int)x0f;
        float fy = ys - y0f, fx = xs - x0f;
        s_o[j] = ((y0 + PAD) * WP + x0 + PAD) * CC;
        float4 wv;
        wv.x = (1.f - fy) * (1.f - fx);
        wv.y = (1.f - fy) * fx;
        wv.z = fy * (1.f - fx);
        wv.w = fy * fx;
        s_w[j] = wv;
    }

    int lane = tid & 31;
    int w    = tid >> 5;
    int gid  = lane >> 2;
    int tig  = lane & 3;

    float d[2][4][4];
    #pragma unroll
    for (int mi = 0; mi < 2; mi++)
        #pragma unroll
        for (int nt = 0; nt < 4; nt++)
            #pragma unroll
            for (int r = 0; r < 4; r++)
                d[mi][nt][r] = 0.f;

    int cil = tid & 15;
    int jg  = tid >> 4;
    const float* xb0 = xt + b * HWP * CC + cil;
    const float4* wf4 = (const float4*)wf;

    for (int chunk = 0; chunk < CC / CICH; chunk++) {
        __syncthreads();

        {
            const float* xb = xb0 + chunk * CICH;
            for (int j = jg; j < NJ; j += 8) {
                int    o  = s_o[j];
                float4 wv = s_w[j];
                float v00 = xb[o];
                float v01 = xb[o + CC];
                float v10 = xb[o + WP * CC];
                float v11 = xb[o + WP * CC + CC];
                float s = wv.x * v00 + wv.y * v01 + wv.z * v10 + wv.w * v11;
                int kk = j >> 5;
                int t  = j & 31;
                s_hi[t * PSTR + cil * KK9 + kk] = f2tf32(s);
            }
        }
        __syncthreads();

        #pragma unroll 2
        for (int sl = 0; sl < 18; sl++) {
            int s = chunk * 18 + sl;
            int aidx = (s * 8 + w * 2) * 32 + lane;
            float4 a0 = wf4[aidx];
            float4 a1 = wf4[aidx + 32];
            uint32_t a0x = __float_as_uint(a0.x), a0y = __float_as_uint(a0.y);
            uint32_t a0z = __float_as_uint(a0.z), a0w = __float_as_uint(a0.w);
            uint32_t a1x = __float_as_uint(a1.x), a1y = __float_as_uint(a1.y);
            uint32_t a1z = __float_as_uint(a1.z), a1w = __float_as_uint(a1.w);

            int krow = sl * 8 + tig;
            #pragma unroll
            for (int nt = 0; nt < 4; nt++) {
                int p = (nt * 8 + gid) * PSTR + krow;
                uint32_t bh0 = __float_as_uint(s_hi[p]);
                uint32_t bh1 = __float_as_uint(s_hi[p + 4]);
                mma_tf32(d[0][nt], a0x, a0y, a0z, a0w, bh0, bh1);
                mma_tf32(d[1][nt], a1x, a1y, a1z, a1w, bh0, bh1);
            }
        }
    }

    // ---- BN (+residual) + ReLU epilogue ----
    #pragma unroll
    for (int mi = 0; mi < 2; mi++) {
        int coa = w * 32 + mi * 16 + gid;
        int cob = coa + 8;
        float inva = gamma[coa] * rsqrtf(var[coa] + 1e-5f);
        float adda = beta[coa] - mean[coa] * inva;
        float invb = gamma[cob] * rsqrtf(var[cob] + 1e-5f);
        float addb = beta[cob] - mean[cob] * invb;

        if (out_nhwc) {
            // stage 1: write padded NHWC directly (no residual)
            float* on = out_nhwc + b * HWP * CC;
            #pragma unroll
            for (int nt = 0; nt < 4; nt++) {
                #pragma unroll
                for (int q = 0; q < 2; q++) {
                    int pix = pix0 + nt * 8 + tig * 2 + q;
                    int pp = (((pix >> 6) + PAD) * WP + (pix & 63) + PAD) * CC;
                    float va = d[mi][nt][q]     * inva + adda;
                    float vb = d[mi][nt][q + 2] * invb + addb;
                    on[pp + coa] = fmaxf(va, 0.f);
                    on[pp + cob] = fmaxf(vb, 0.f);
                }
            }
        } else {
            int basea = ((b * CC + coa) << 12) + pix0 + tig * 2;
            int baseb = ((b * CC + cob) << 12) + pix0 + tig * 2;
            #pragma unroll
            for (int nt = 0; nt < 4; nt++) {
                float2 ra, rb;
                ra.x = d[mi][nt][0] * inva + adda;
                ra.y = d[mi][nt][1] * inva + adda;
                rb.x = d[mi][nt][2] * invb + addb;
                rb.y = d[mi][nt][3] * invb + addb;
                if (resid) {
                    float2 qa = *(const float2*)(resid + basea + nt * 8);
                    float2 qb = *(const float2*)(resid + baseb + nt * 8);
                    ra.x += qa.x; ra.y += qa.y;
                    rb.x += qb.x; rb.y += qb.y;
                }
                ra.x = fmaxf(ra.x, 0.f); ra.y = fmaxf(ra.y, 0.f);
                rb.x = fmaxf(rb.x, 0.f); rb.y = fmaxf(rb.y, 0.f);
                *(float2*)(out + basea + nt * 8) = ra;
                *(float2*)(out + baseb + nt * 8) = rb;
            }
        }
    }
}

// ---------------- launch ----------------
extern "C" void kernel_launch(void* const* d_in, const int* in_sizes, int n_in,
                              void* d_out, int out_size)
{
    const float* x      = (const float*)d_in[0];
    const float* w_off1 = (const float*)d_in[1];
    const float* b_off1 = (const float*)d_in[2];
    const float* w_dc1  = (const float*)d_in[3];
    const float* g1     = (const float*)d_in[4];
    const float* beta1  = (const float*)d_in[5];
    const float* m1     = (const float*)d_in[6];
    const float* v1     = (const float*)d_in[7];
    const float* w_off2 = (const float*)d_in[8];
    const float* b_off2 = (const float*)d_in[9];
    const float* w_dc2  = (const float*)d_in[10];
    const float* g2     = (const float*)d_in[11];
    const float* beta2  = (const float*)d_in[12];
    const float* m2     = (const float*)d_in[13];
    const float* v2     = (const float*)d_in[14];
    float* out = (float*)d_out;

    float *off1, *off2, *xt, *xt2, *wf1, *wf2, *wo1, *wo2;
    cudaGetSymbolAddress((void**)&off1, g_off1);
    cudaGetSymbolAddress((void**)&off2, g_off2);
    cudaGetSymbolAddress((void**)&xt,   g_xt);
    cudaGetSymbolAddress((void**)&xt2,  g_xt2);
    cudaGetSymbolAddress((void**)&wf1,  g_wf1);
    cudaGetSymbolAddress((void**)&wf2,  g_wf2);
    cudaGetSymbolAddress((void**)&wo1,  g_wo1);
    cudaGetSymbolAddress((void**)&wo2,  g_wo2);

    dim3 trGrid(HW / 32, CC / 32, BB), trBlk(32, 8);
    int zpGrid = (BB * HWP * CC / 4) / 512;

    // zero both padded buffers (borders stay 0; interiors rewritten below)
    zeropad_kernel<<<zpGrid, 512>>>(xt);
    zeropad_kernel<<<zpGrid, 512>>>(xt2);
    prepack_kernel<<<NKSTEP, 256>>>(w_dc1, w_dc2);
    prepack_off_kernel<<<NKSTEP, 64>>>(w_off1, w_off2);

    // stage 1: transpose input, offconv + deform (deform writes padded NHWC)
    transpose_kernel<<<trGrid, trBlk>>>(x, xt);
    offconv_tc_kernel<<<BB * HW / DT, 128>>>(xt, wo1, b_off1, off1);
    deform_kernel<<<BB * HW / DT, 128>>>(xt, off1, wf1, g1, beta1, m1, v1,
                                         nullptr, nullptr, xt2);
    // stage 2: reads stage-1 NHWC output directly (no transpose)
    offconv_tc_kernel<<<BB * HW / DT, 128>>>(xt2, wo2, b_off2, off2);
    deform_kernel<<<BB * HW / DT, 128>>>(xt2, off2, wf2, g2, beta2, m2, v2,
                                         x, out, nullptr);
}